// round 3
// baseline (speedup 1.0000x reference)
#include <cuda_runtime.h>
#include <math.h>

#define NB 16
#define H 512
#define W 512
#define RPB 32
#define MUF 5.0f
#define KKINV (1.0f/961.0f)
#define NBLK (NB * (H / RPB))   // 256

// smem layout (floats):
//   s_v   : 32*512       = 16384
//   sP    : 4*544        = 2176
//   s_wsum: 16
//   s_red : 64
//   s_flag: 1
#define OFF_SP   (32 * W)
#define OFF_WSUM (OFF_SP + 4 * 544)
#define OFF_RED  (OFF_WSUM + 16)
#define OFF_FLAG (OFF_RED + 64)
#define SMEM_FLOATS (OFF_FLAG + 1)
#define SMEM_BYTES (SMEM_FLOATS * 4)

__device__ float4 g_part4[NBLK];
__device__ unsigned int g_count;    // zero-initialized; self-resetting

__global__ void __launch_bounds__(512, 2)
fused_kernel(const float* __restrict__ pred, const float* __restrict__ mask,
             float* __restrict__ out) {
    extern __shared__ float smem[];
    float* s_v    = smem;
    float* s_P    = smem + OFF_SP;     // [4][544]: 16 left-pad | 512 | 16 right-pad
    float* s_wsum = smem + OFF_WSUM;   // [4][4]
    float* s_red  = smem + OFF_RED;    // [16][4]
    float* s_flag = smem + OFF_FLAG;

    const int t  = threadIdx.x;
    const int b  = blockIdx.x >> 4;
    const int r0 = (blockIdx.x & 15) * RPB;

    const float* mb = mask + (size_t)b * H * W;
    const float* pb = pred + (size_t)(b * 2 + 1) * H * W;   // channel-1 logits

    // zero the 4 groups' left pads (P[c-16] for c<16)
    if (t < 64) s_P[(t >> 4) * 544 + (t & 15)] = 0.f;

    // ---------- phase 1: vertical sliding box sum, one thread per column ----------
    {
        const int c = t;
        float s = 0.f;
        int lo = r0 - 15; if (lo < 0) lo = 0;
        const int hi = r0 + 15;                    // r0 <= 480 -> hi <= 495 < H
        for (int j = lo; j <= hi; ++j) s += mb[j * W + c];

        #pragma unroll 8
        for (int k = 0; k < RPB; ++k) {
            s_v[k * W + c] = s;
            int ar = r0 + k + 16;
            int sr = r0 + k - 15;
            if (ar < H)  s += mb[ar * W + c];
            if (sr >= 0) s -= mb[sr * W + c];
        }
    }
    __syncthreads();

    // ---------- phase 2: horizontal prefix-scan box + elementwise ----------
    const int g    = t >> 7;          // row group 0..3
    const int tg   = t & 127;
    const int wg   = (t >> 5) & 3;
    const int lane = t & 31;
    const int c0   = tg * 4;
    float* gP = s_P + g * 544;

    float a0 = 0.f, a1 = 0.f, a2 = 0.f, a3 = 0.f;

    for (int it = 0; it < 8; ++it) {
        const int lr = it * 4 + g;                 // local row 0..31
        const int rr = r0 + lr;

        float4 v4 = *(const float4*)&s_v[lr * W + c0];
        float l0 = v4.x;
        float l1 = l0 + v4.y;
        float l2 = l1 + v4.z;
        float l3 = l2 + v4.w;
        float tot = l3;

        float x = tot;
        #pragma unroll
        for (int d = 1; d < 32; d <<= 1) {
            float n = __shfl_up_sync(0xffffffffu, x, d);
            if (lane >= d) x += n;
        }
        if (lane == 31) s_wsum[g * 4 + wg] = x;
        __syncthreads();

        float woff = x - tot;
        #pragma unroll
        for (int w = 0; w < 4; ++w) if (w < wg) woff += s_wsum[g * 4 + w];

        float4 P4 = make_float4(woff + l0, woff + l1, woff + l2, woff + l3);
        *(float4*)&gP[16 + c0] = P4;
        if (tg == 127) {                           // replicate P[511] into right pad
            float4 rep = make_float4(P4.w, P4.w, P4.w, P4.w);
            *(float4*)&gP[528] = rep;
            *(float4*)&gP[532] = rep;
            *(float4*)&gP[536] = rep;
            *(float4*)&gP[540] = rep;
        }
        __syncthreads();

        float4 Pa = *(const float4*)&gP[16 + c0 + 12];  // P[c0+12..15]
        float4 Pb = *(const float4*)&gP[16 + c0 + 16];  // P[c0+16..19]
        float4 Pl = *(const float4*)&gP[c0];            // P[c0-16..-13]

        float win[4];
        win[0] = Pa.w - Pl.x;
        win[1] = Pb.x - Pl.y;
        win[2] = Pb.y - Pl.z;
        win[3] = Pb.z - Pl.w;

        float4 m4 = *(const float4*)(mb + (size_t)rr * W + c0);
        float4 p4 = *(const float4*)(pb + (size_t)rr * W + c0);
        float mv[4] = {m4.x, m4.y, m4.z, m4.w};
        float pv[4] = {p4.x, p4.y, p4.z, p4.w};

        #pragma unroll
        for (int i = 0; i < 4; ++i) {
            float box  = win[i] * KKINV;
            float m    = mv[i];
            float p    = pv[i];
            float weit = 1.0f + MUF * fabsf(box - m);

            float bce = fmaxf(p, 0.0f) - p * m + log1pf(__expf(-fabsf(p)));
            float ps  = 1.0f / (1.0f + __expf(-p));

            a0 += weit * bce;
            a1 += weit;
            a2 += ps * m * weit;
            a3 += (ps + m) * weit;
        }
    }

    // ---------- deterministic block reduction ----------
    #pragma unroll
    for (int d = 16; d > 0; d >>= 1) {
        a0 += __shfl_down_sync(0xffffffffu, a0, d);
        a1 += __shfl_down_sync(0xffffffffu, a1, d);
        a2 += __shfl_down_sync(0xffffffffu, a2, d);
        a3 += __shfl_down_sync(0xffffffffu, a3, d);
    }
    const int wid = t >> 5;
    if (lane == 0) {
        s_red[wid * 4 + 0] = a0;
        s_red[wid * 4 + 1] = a1;
        s_red[wid * 4 + 2] = a2;
        s_red[wid * 4 + 3] = a3;
    }
    __syncthreads();

    if (t == 0) {
        float s0 = 0.f, s1 = 0.f, s2 = 0.f, s3 = 0.f;
        #pragma unroll
        for (int w = 0; w < 16; ++w) {
            s0 += s_red[w * 4 + 0];
            s1 += s_red[w * 4 + 1];
            s2 += s_red[w * 4 + 2];
            s3 += s_red[w * 4 + 3];
        }
        g_part4[blockIdx.x] = make_float4(s0, s1, s2, s3);
        __threadfence();
        unsigned int old = atomicAdd(&g_count, 1u);
        s_flag[0] = (old == NBLK - 1) ? 1.f : 0.f;
    }
    __syncthreads();

    // ---------- last block finalizes ----------
    if (s_flag[0] != 0.f) {
        if (t < NB) {
            float s0 = 0.f, s1 = 0.f, s2 = 0.f, s3 = 0.f;
            #pragma unroll
            for (int k = 0; k < 16; ++k) {
                float4 v = __ldcg(&g_part4[t * 16 + k]);
                s0 += v.x; s1 += v.y; s2 += v.z; s3 += v.w;
            }
            float wbce = s0 / s1;
            float wiou = 1.0f - (s2 + 1.0f) / (s3 - s2 + 1.0f);
            s_red[t] = wbce + wiou;
        }
        __syncthreads();
        if (t == 0) {
            float s = 0.f;
            #pragma unroll
            for (int k = 0; k < NB; ++k) s += s_red[k];
            out[0] = s * (1.0f / NB);
            g_count = 0;                 // self-reset for next replay
        }
    }
}

extern "C" void kernel_launch(void* const* d_in, const int* in_sizes, int n_in,
                              void* d_out, int out_size) {
    const float* pred = (const float*)d_in[0];
    const float* mask = (const float*)d_in[1];
    if (n_in >= 2 && in_sizes[0] == NB * H * W && in_sizes[1] == NB * 2 * H * W) {
        mask = (const float*)d_in[0];
        pred = (const float*)d_in[1];
    }
    float* out = (float*)d_out;

    static bool attr_set = false;
    if (!attr_set) {
        cudaFuncSetAttribute(fused_kernel,
                             cudaFuncAttributeMaxDynamicSharedMemorySize, SMEM_BYTES);
        attr_set = true;
    }
    fused_kernel<<<NBLK, 512, SMEM_BYTES>>>(pred, mask, out);
}

// round 4
// speedup vs baseline: 1.4016x; 1.4016x over previous
#include <cuda_runtime.h>
#include <math.h>

#define NB 16
#define H 512
#define W 512
#define KR 15
#define KKINV (1.0f/961.0f)
#define MUF 5.0f
#define NBLK_B (NB * H)     // 8192 blocks in kernel B

__device__ float g_vsum[NB * H * W];     // vertical box sums (16 MB)
__device__ float4 g_part4[NBLK_B];       // per-(b,row) partials
__device__ unsigned int g_count;         // zero-init; self-resetting

// ================= Kernel A: vertical sliding box sum =================
#define RPB 32
__global__ void vert_kernel(const float* __restrict__ mask) {
    const int segs = H / RPB;            // 16
    int b  = blockIdx.x / segs;
    int r0 = (blockIdx.x % segs) * RPB;
    int c  = threadIdx.x;                // 512 threads, one per column

    const float* mb = mask + (size_t)b * H * W;
    float* vb = g_vsum + (size_t)b * H * W;

    float s = 0.0f;
    int lo = r0 - KR; if (lo < 0) lo = 0;
    int hi = r0 + KR; if (hi > H - 1) hi = H - 1;
    #pragma unroll 4
    for (int j = lo; j <= hi; ++j) s += mb[j * W + c];

    #pragma unroll
    for (int r = r0; r < r0 + RPB; ++r) {
        vb[r * W + c] = s;
        int add = r + KR + 1;
        int sub = r - KR;
        if (add < H) s += mb[add * W + c];
        if (sub >= 0) s -= mb[sub * W + c];
    }
}

// ========== Kernel B: horizontal box + elementwise + reduce + finalize ==========
// one block per (b, row); 128 threads, 4 consecutive columns per thread
__global__ void main_kernel(const float* __restrict__ pred,
                            const float* __restrict__ mask,
                            float* __restrict__ out) {
    __shared__ float sP[W + 32];    // [16 left-pad | 512 prefix | 16 right-pad]
    __shared__ float wsum[4];
    __shared__ float red[16];       // also reused for finalize losses
    __shared__ float flag;

    const int b = blockIdx.x >> 9;
    const int r = blockIdx.x & (H - 1);
    const int t = threadIdx.x;      // 0..127
    const int lane = t & 31;
    const int wid  = t >> 5;
    const int c0 = t * 4;

    // zero left pad
    if (t < 4) *(float4*)&sP[t * 4] = make_float4(0.f, 0.f, 0.f, 0.f);

    const size_t rowOff = (size_t)b * H * W + (size_t)r * W;
    const float4 v4 = *(const float4*)(g_vsum + rowOff + c0);

    // thread-local inclusive prefix
    float l0 = v4.x;
    float l1 = l0 + v4.y;
    float l2 = l1 + v4.z;
    float l3 = l2 + v4.w;
    float tot = l3;

    // warp inclusive scan of thread totals
    float x = tot;
    #pragma unroll
    for (int d = 1; d < 32; d <<= 1) {
        float n = __shfl_up_sync(0xffffffffu, x, d);
        if (lane >= d) x += n;
    }
    if (lane == 31) wsum[wid] = x;
    __syncthreads();
    float woff = x - tot;
    #pragma unroll
    for (int w = 0; w < 4; ++w) if (w < wid) woff += wsum[w];

    float4 P4 = make_float4(woff + l0, woff + l1, woff + l2, woff + l3);
    *(float4*)&sP[16 + c0] = P4;
    if (t == 127) {                 // replicate P[511] into right pad
        float4 rep = make_float4(P4.w, P4.w, P4.w, P4.w);
        *(float4*)&sP[528] = rep;
        *(float4*)&sP[532] = rep;
        *(float4*)&sP[536] = rep;
        *(float4*)&sP[540] = rep;
    }
    __syncthreads();

    // 31-wide window via prefix differences (aligned LDS.128)
    float4 Pa = *(const float4*)&sP[16 + c0 + 12];
    float4 Pb = *(const float4*)&sP[16 + c0 + 16];
    float4 Pl = *(const float4*)&sP[c0];

    float win[4];
    win[0] = Pa.w - Pl.x;
    win[1] = Pb.x - Pl.y;
    win[2] = Pb.y - Pl.z;
    win[3] = Pb.z - Pl.w;

    const float4 m4 = *(const float4*)(mask + rowOff + c0);
    const size_t predOff = (((size_t)b * 2 + 1) * H + r) * W;
    const float4 p4 = *(const float4*)(pred + predOff + c0);
    float mv[4] = {m4.x, m4.y, m4.z, m4.w};
    float pv[4] = {p4.x, p4.y, p4.z, p4.w};

    float a0 = 0.f, a1 = 0.f, a2 = 0.f, a3 = 0.f;
    #pragma unroll
    for (int i = 0; i < 4; ++i) {
        float box  = win[i] * KKINV;
        float m    = mv[i];
        float p    = pv[i];
        float weit = 1.0f + MUF * fabsf(box - m);

        float bce = fmaxf(p, 0.0f) - p * m + log1pf(__expf(-fabsf(p)));
        float ps  = 1.0f / (1.0f + __expf(-p));

        a0 += weit * bce;
        a1 += weit;
        a2 += ps * m * weit;
        a3 += (ps + m) * weit;
    }

    // deterministic block reduction
    #pragma unroll
    for (int d = 16; d > 0; d >>= 1) {
        a0 += __shfl_down_sync(0xffffffffu, a0, d);
        a1 += __shfl_down_sync(0xffffffffu, a1, d);
        a2 += __shfl_down_sync(0xffffffffu, a2, d);
        a3 += __shfl_down_sync(0xffffffffu, a3, d);
    }
    if (lane == 0) {
        red[wid * 4 + 0] = a0;
        red[wid * 4 + 1] = a1;
        red[wid * 4 + 2] = a2;
        red[wid * 4 + 3] = a3;
    }
    __syncthreads();
    if (t == 0) {
        float s0 = red[0] + red[4] + red[8]  + red[12];
        float s1 = red[1] + red[5] + red[9]  + red[13];
        float s2 = red[2] + red[6] + red[10] + red[14];
        float s3 = red[3] + red[7] + red[11] + red[15];
        g_part4[blockIdx.x] = make_float4(s0, s1, s2, s3);
        __threadfence();
        unsigned int old = atomicAdd(&g_count, 1u);
        flag = (old == NBLK_B - 1) ? 1.f : 0.f;
    }
    __syncthreads();

    // ---------- last block finalizes ----------
    if (flag != 0.f) {
        const int bb = t >> 3;      // batch 0..15
        const int j  = t & 7;       // chunk 0..7
        float s0 = 0.f, s1 = 0.f, s2 = 0.f, s3 = 0.f;
        const float4* gp = g_part4 + bb * H + j * 64;
        #pragma unroll 8
        for (int k = 0; k < 64; ++k) {
            float4 v = __ldcg(&gp[k]);
            s0 += v.x; s1 += v.y; s2 += v.z; s3 += v.w;
        }
        #pragma unroll
        for (int d = 4; d > 0; d >>= 1) {
            s0 += __shfl_down_sync(0xffffffffu, s0, d, 8);
            s1 += __shfl_down_sync(0xffffffffu, s1, d, 8);
            s2 += __shfl_down_sync(0xffffffffu, s2, d, 8);
            s3 += __shfl_down_sync(0xffffffffu, s3, d, 8);
        }
        if (j == 0) {
            float wbce = s0 / s1;
            float wiou = 1.0f - (s2 + 1.0f) / (s3 - s2 + 1.0f);
            red[bb] = wbce + wiou;
        }
        __syncthreads();
        if (t == 0) {
            float s = 0.f;
            #pragma unroll
            for (int k = 0; k < NB; ++k) s += red[k];
            out[0] = s * (1.0f / NB);
            g_count = 0;            // self-reset for next graph replay
        }
    }
}

extern "C" void kernel_launch(void* const* d_in, const int* in_sizes, int n_in,
                              void* d_out, int out_size) {
    const float* pred = (const float*)d_in[0];
    const float* mask = (const float*)d_in[1];
    if (n_in >= 2 && in_sizes[0] == NB * H * W && in_sizes[1] == NB * 2 * H * W) {
        mask = (const float*)d_in[0];
        pred = (const float*)d_in[1];
    }
    float* out = (float*)d_out;

    vert_kernel<<<NB * (H / RPB), W>>>(mask);
    main_kernel<<<NBLK_B, 128>>>(pred, mask, out);
}

// round 5
// speedup vs baseline: 1.5631x; 1.1153x over previous
#include <cuda_runtime.h>
#include <math.h>

#define NB 16
#define H 512
#define W 512
#define KR 15
#define KKINV (1.0f/961.0f)
#define MUF 5.0f
#define NBLK_B (NB * H)     // 8192 blocks in kernel B

__device__ float g_vsum[NB * H * W];     // vertical box sums (16 MB)
__device__ float4 g_part4[NBLK_B];       // per-(b,row) partials
__device__ unsigned int g_count;         // zero-init; self-resetting

// ================= Kernel A: vertical sliding box sum =================
#define RPB 32
__global__ void vert_kernel(const float* __restrict__ mask) {
    const int segs = H / RPB;            // 16
    int b  = blockIdx.x / segs;
    int r0 = (blockIdx.x % segs) * RPB;
    int c  = threadIdx.x;                // 512 threads, one per column

    const float* mb = mask + (size_t)b * H * W;
    float* vb = g_vsum + (size_t)b * H * W;

    float s = 0.0f;
    int lo = r0 - KR; if (lo < 0) lo = 0;
    int hi = r0 + KR; if (hi > H - 1) hi = H - 1;
    #pragma unroll 4
    for (int j = lo; j <= hi; ++j) s += mb[j * W + c];

    #pragma unroll
    for (int r = r0; r < r0 + RPB; ++r) {
        vb[r * W + c] = s;
        int add = r + KR + 1;
        int sub = r - KR;
        if (add < H) s += mb[add * W + c];
        if (sub >= 0) s -= mb[sub * W + c];
    }
}

// ========== Kernel B: horizontal box + elementwise + reduce + finalize ==========
// one block per (b, row); 128 threads, 4 consecutive columns per thread
__global__ void main_kernel(const float* __restrict__ pred,
                            const float* __restrict__ mask,
                            float* __restrict__ out) {
    __shared__ float sP[W + 32];    // [16 left-pad | 512 prefix | 16 right-pad]
    __shared__ float wsum[4];
    __shared__ float red[16];       // also reused for finalize losses
    __shared__ float flag;

    const int b = blockIdx.x >> 9;
    const int r = blockIdx.x & (H - 1);
    const int t = threadIdx.x;      // 0..127
    const int lane = t & 31;
    const int wid  = t >> 5;
    const int c0 = t * 4;

    // zero left pad
    if (t < 4) *(float4*)&sP[t * 4] = make_float4(0.f, 0.f, 0.f, 0.f);

    const size_t rowOff = (size_t)b * H * W + (size_t)r * W;
    const float4 v4 = *(const float4*)(g_vsum + rowOff + c0);

    // thread-local inclusive prefix
    float l0 = v4.x;
    float l1 = l0 + v4.y;
    float l2 = l1 + v4.z;
    float l3 = l2 + v4.w;
    float tot = l3;

    // warp inclusive scan of thread totals
    float x = tot;
    #pragma unroll
    for (int d = 1; d < 32; d <<= 1) {
        float n = __shfl_up_sync(0xffffffffu, x, d);
        if (lane >= d) x += n;
    }
    if (lane == 31) wsum[wid] = x;
    __syncthreads();
    float woff = x - tot;
    #pragma unroll
    for (int w = 0; w < 4; ++w) if (w < wid) woff += wsum[w];

    float4 P4 = make_float4(woff + l0, woff + l1, woff + l2, woff + l3);
    *(float4*)&sP[16 + c0] = P4;
    if (t == 127) {                 // replicate P[511] into right pad
        float4 rep = make_float4(P4.w, P4.w, P4.w, P4.w);
        *(float4*)&sP[528] = rep;
        *(float4*)&sP[532] = rep;
        *(float4*)&sP[536] = rep;
        *(float4*)&sP[540] = rep;
    }
    __syncthreads();

    // 31-wide window via prefix differences (aligned LDS.128)
    float4 Pa = *(const float4*)&sP[16 + c0 + 12];
    float4 Pb = *(const float4*)&sP[16 + c0 + 16];
    float4 Pl = *(const float4*)&sP[c0];

    float win[4];
    win[0] = Pa.w - Pl.x;
    win[1] = Pb.x - Pl.y;
    win[2] = Pb.y - Pl.z;
    win[3] = Pb.z - Pl.w;

    const float4 m4 = *(const float4*)(mask + rowOff + c0);
    const size_t predOff = (((size_t)b * 2 + 1) * H + r) * W;
    const float4 p4 = *(const float4*)(pred + predOff + c0);
    float mv[4] = {m4.x, m4.y, m4.z, m4.w};
    float pv[4] = {p4.x, p4.y, p4.z, p4.w};

    float a0 = 0.f, a1 = 0.f, a2 = 0.f, a3 = 0.f;
    #pragma unroll
    for (int i = 0; i < 4; ++i) {
        float box  = win[i] * KKINV;
        float m    = mv[i];
        float p    = pv[i];
        float weit = 1.0f + MUF * fabsf(box - m);

        float e   = __expf(-fabsf(p));            // MUFU.EX2
        float bce = fmaxf(p, 0.0f) - p * m + __logf(1.0f + e);   // MUFU.LG2
        float rcp = __fdividef(1.0f, 1.0f + e);   // MUFU.RCP
        float ps  = (p >= 0.0f) ? rcp : e * rcp;  // sigmoid(p)

        a0 += weit * bce;
        a1 += weit;
        a2 += ps * m * weit;
        a3 += (ps + m) * weit;
    }

    // deterministic block reduction
    #pragma unroll
    for (int d = 16; d > 0; d >>= 1) {
        a0 += __shfl_down_sync(0xffffffffu, a0, d);
        a1 += __shfl_down_sync(0xffffffffu, a1, d);
        a2 += __shfl_down_sync(0xffffffffu, a2, d);
        a3 += __shfl_down_sync(0xffffffffu, a3, d);
    }
    if (lane == 0) {
        red[wid * 4 + 0] = a0;
        red[wid * 4 + 1] = a1;
        red[wid * 4 + 2] = a2;
        red[wid * 4 + 3] = a3;
    }
    __syncthreads();
    if (t == 0) {
        float s0 = red[0] + red[4] + red[8]  + red[12];
        float s1 = red[1] + red[5] + red[9]  + red[13];
        float s2 = red[2] + red[6] + red[10] + red[14];
        float s3 = red[3] + red[7] + red[11] + red[15];
        // L2-visible partial write, then release-ordered counter bump.
        // No __threadfence: gpu-scope fence emits CCTL.IVALL (full L1D flush)
        // per block, which wrecked L1 for co-resident blocks in round 4.
        __stcg(&g_part4[blockIdx.x], make_float4(s0, s1, s2, s3));
        unsigned int old;
        asm volatile("atom.acq_rel.gpu.global.add.u32 %0, [%1], %2;"
                     : "=r"(old) : "l"(&g_count), "r"(1u) : "memory");
        flag = (old == NBLK_B - 1) ? 1.f : 0.f;
    }
    __syncthreads();

    // ---------- last block finalizes ----------
    if (flag != 0.f) {
        const int bb = t >> 3;      // batch 0..15
        const int j  = t & 7;       // chunk 0..7
        float s0 = 0.f, s1 = 0.f, s2 = 0.f, s3 = 0.f;
        const float4* gp = g_part4 + bb * H + j * 64;
        #pragma unroll 8
        for (int k = 0; k < 64; ++k) {
            float4 v = __ldcg(&gp[k]);
            s0 += v.x; s1 += v.y; s2 += v.z; s3 += v.w;
        }
        #pragma unroll
        for (int d = 4; d > 0; d >>= 1) {
            s0 += __shfl_down_sync(0xffffffffu, s0, d, 8);
            s1 += __shfl_down_sync(0xffffffffu, s1, d, 8);
            s2 += __shfl_down_sync(0xffffffffu, s2, d, 8);
            s3 += __shfl_down_sync(0xffffffffu, s3, d, 8);
        }
        if (j == 0) {
            float wbce = s0 / s1;
            float wiou = 1.0f - (s2 + 1.0f) / (s3 - s2 + 1.0f);
            red[bb] = wbce + wiou;
        }
        __syncthreads();
        if (t == 0) {
            float s = 0.f;
            #pragma unroll
            for (int k = 0; k < NB; ++k) s += red[k];
            out[0] = s * (1.0f / NB);
            g_count = 0;            // self-reset for next graph replay
        }
    }
}

extern "C" void kernel_launch(void* const* d_in, const int* in_sizes, int n_in,
                              void* d_out, int out_size) {
    const float* pred = (const float*)d_in[0];
    const float* mask = (const float*)d_in[1];
    if (n_in >= 2 && in_sizes[0] == NB * H * W && in_sizes[1] == NB * 2 * H * W) {
        mask = (const float*)d_in[0];
        pred = (const float*)d_in[1];
    }
    float* out = (float*)d_out;

    vert_kernel<<<NB * (H / RPB), W>>>(mask);
    main_kernel<<<NBLK_B, 128>>>(pred, mask, out);
}

// round 6
// speedup vs baseline: 1.5840x; 1.0133x over previous
#include <cuda_runtime.h>
#include <cuda_fp16.h>
#include <math.h>

#define NB 16
#define H 512
#define W 512
#define KR 15
#define KKINV (1.0f/961.0f)
#define MUF 5.0f
#define NBLK_B (NB * (H / 4))        // 2048 blocks in kernel B

__device__ __half2 g_vsum[NB * H * (W / 2)];   // vertical box sums, fp16 (8 MB)
__device__ float4 g_part4[NBLK_B];             // per-block partials
__device__ unsigned int g_count;               // zero-init; self-resetting

// ================= Kernel A: vertical sliding box sum (fp16 out) =================
#define RPB 32
__global__ void vert_kernel(const float* __restrict__ mask) {
    const int segs = H / RPB;        // 16
    const int b  = blockIdx.x / segs;
    const int r0 = (blockIdx.x % segs) * RPB;
    const int t  = threadIdx.x;      // 0..255, owns cols 2t, 2t+1

    const float2* mb2 = (const float2*)(mask + (size_t)b * H * W);
    __half2* vb = g_vsum + (size_t)b * H * (W / 2);

    float sx = 0.f, sy = 0.f;
    int lo = r0 - KR; if (lo < 0) lo = 0;
    int hi = r0 + KR; if (hi > H - 1) hi = H - 1;
    #pragma unroll 4
    for (int j = lo; j <= hi; ++j) {
        float2 v = __ldcg(&mb2[j * (W / 2) + t]);
        sx += v.x; sy += v.y;
    }

    #pragma unroll
    for (int r = r0; r < r0 + RPB; ++r) {
        __stcg(&vb[r * (W / 2) + t], __floats2half2_rn(sx, sy));
        int add = r + KR + 1;
        int sub = r - KR;
        if (add < H) {
            float2 v = __ldcg(&mb2[add * (W / 2) + t]);
            sx += v.x; sy += v.y;
        }
        if (sub >= 0) {
            float2 v = __ldcg(&mb2[sub * (W / 2) + t]);
            sx -= v.x; sy -= v.y;
        }
    }
}

// ========== Kernel B: horizontal box + elementwise + reduce + finalize ==========
// 512 threads = 4 row-groups of 128; block handles 4 consecutive rows
__global__ void __launch_bounds__(512)
main_kernel(const float* __restrict__ pred,
            const float* __restrict__ mask,
            float* __restrict__ out) {
    __shared__ float sP[4][544];     // per-group: [16 pad | 512 prefix | 16 pad]
    __shared__ float wsum[4][4];
    __shared__ float red[64];        // 16 warps x 4
    __shared__ float flag;

    const int t    = threadIdx.x;
    const int g    = t >> 7;         // row group 0..3
    const int tg   = t & 127;
    const int wg   = (t >> 5) & 3;
    const int lane = t & 31;
    const int c0   = tg * 4;

    const int b = blockIdx.x >> 7;
    const int r = (blockIdx.x & 127) * 4 + g;
    float* gP = sP[g];

    // zero left pads
    if (tg < 4) *(float4*)&gP[tg * 4] = make_float4(0.f, 0.f, 0.f, 0.f);

    // ---- load vsum (fp16) ----
    const __half2* vb = g_vsum + ((size_t)b * H + r) * (W / 2);
    __half2 h01 = __ldcg(&vb[tg * 2 + 0]);
    __half2 h23 = __ldcg(&vb[tg * 2 + 1]);
    float2 f01 = __half22float2(h01);
    float2 f23 = __half22float2(h23);

    // streaming elementwise inputs (issue early)
    const size_t rowOff = ((size_t)b * H + r) * W;
    const float4 m4 = __ldcg((const float4*)(mask + rowOff + c0));
    const size_t predOff = (((size_t)b * 2 + 1) * H + r) * W;
    const float4 p4 = __ldcg((const float4*)(pred + predOff + c0));

    // thread-local inclusive prefix
    float l0 = f01.x;
    float l1 = l0 + f01.y;
    float l2 = l1 + f23.x;
    float l3 = l2 + f23.y;
    float tot = l3;

    // warp inclusive scan of thread totals
    float x = tot;
    #pragma unroll
    for (int d = 1; d < 32; d <<= 1) {
        float n = __shfl_up_sync(0xffffffffu, x, d);
        if (lane >= d) x += n;
    }
    if (lane == 31) wsum[g][wg] = x;
    __syncthreads();
    float woff = x - tot;
    #pragma unroll
    for (int w = 0; w < 4; ++w) if (w < wg) woff += wsum[g][w];

    float4 P4 = make_float4(woff + l0, woff + l1, woff + l2, woff + l3);
    *(float4*)&gP[16 + c0] = P4;
    if (tg == 127) {                 // replicate P[511] into right pad
        float4 rep = make_float4(P4.w, P4.w, P4.w, P4.w);
        *(float4*)&gP[528] = rep;
        *(float4*)&gP[532] = rep;
        *(float4*)&gP[536] = rep;
        *(float4*)&gP[540] = rep;
    }
    __syncthreads();

    // 31-wide window via prefix differences (aligned LDS.128)
    float4 Pa = *(const float4*)&gP[16 + c0 + 12];
    float4 Pb = *(const float4*)&gP[16 + c0 + 16];
    float4 Pl = *(const float4*)&gP[c0];

    float win[4];
    win[0] = Pa.w - Pl.x;
    win[1] = Pb.x - Pl.y;
    win[2] = Pb.y - Pl.z;
    win[3] = Pb.z - Pl.w;

    float mv[4] = {m4.x, m4.y, m4.z, m4.w};
    float pv[4] = {p4.x, p4.y, p4.z, p4.w};

    float a0 = 0.f, a1 = 0.f, a2 = 0.f, a3 = 0.f;
    #pragma unroll
    for (int i = 0; i < 4; ++i) {
        float box  = win[i] * KKINV;
        float m    = mv[i];
        float p    = pv[i];
        float weit = 1.0f + MUF * fabsf(box - m);

        float e   = __expf(-fabsf(p));                          // MUFU.EX2
        float bce = fmaxf(p, 0.0f) - p * m + __logf(1.0f + e);  // MUFU.LG2
        float rcp = __fdividef(1.0f, 1.0f + e);                 // MUFU.RCP
        float ps  = (p >= 0.0f) ? rcp : e * rcp;                // sigmoid(p)

        a0 += weit * bce;
        a1 += weit;
        a2 += ps * m * weit;
        a3 += (ps + m) * weit;
    }

    // deterministic block reduction (16 warps)
    #pragma unroll
    for (int d = 16; d > 0; d >>= 1) {
        a0 += __shfl_down_sync(0xffffffffu, a0, d);
        a1 += __shfl_down_sync(0xffffffffu, a1, d);
        a2 += __shfl_down_sync(0xffffffffu, a2, d);
        a3 += __shfl_down_sync(0xffffffffu, a3, d);
    }
    const int wid = t >> 5;
    if (lane == 0) {
        red[wid * 4 + 0] = a0;
        red[wid * 4 + 1] = a1;
        red[wid * 4 + 2] = a2;
        red[wid * 4 + 3] = a3;
    }
    __syncthreads();
    if (t == 0) {
        float s0 = 0.f, s1 = 0.f, s2 = 0.f, s3 = 0.f;
        #pragma unroll
        for (int w = 0; w < 16; ++w) {
            s0 += red[w * 4 + 0];
            s1 += red[w * 4 + 1];
            s2 += red[w * 4 + 2];
            s3 += red[w * 4 + 3];
        }
        // L2-visible write + release/acquire atomic (no CCTL.IVALL L1 flush)
        __stcg(&g_part4[blockIdx.x], make_float4(s0, s1, s2, s3));
        unsigned int old;
        asm volatile("atom.acq_rel.gpu.global.add.u32 %0, [%1], %2;"
                     : "=r"(old) : "l"(&g_count), "r"(1u) : "memory");
        flag = (old == NBLK_B - 1) ? 1.f : 0.f;
    }
    __syncthreads();

    // ---------- last block finalizes ----------
    if (flag != 0.f) {
        if (t < 128) {
            const int bb = t >> 3;      // batch 0..15
            const int j  = t & 7;       // chunk 0..7
            float s0 = 0.f, s1 = 0.f, s2 = 0.f, s3 = 0.f;
            const float4* gp = g_part4 + bb * 128 + j * 16;
            #pragma unroll
            for (int k = 0; k < 16; ++k) {
                float4 v = __ldcg(&gp[k]);
                s0 += v.x; s1 += v.y; s2 += v.z; s3 += v.w;
            }
            #pragma unroll
            for (int d = 4; d > 0; d >>= 1) {
                s0 += __shfl_down_sync(0xffffffffu, s0, d, 8);
                s1 += __shfl_down_sync(0xffffffffu, s1, d, 8);
                s2 += __shfl_down_sync(0xffffffffu, s2, d, 8);
                s3 += __shfl_down_sync(0xffffffffu, s3, d, 8);
            }
            if (j == 0) {
                float wbce = s0 / s1;
                float wiou = 1.0f - (s2 + 1.0f) / (s3 - s2 + 1.0f);
                red[bb] = wbce + wiou;
            }
        }
        __syncthreads();
        if (t == 0) {
            float s = 0.f;
            #pragma unroll
            for (int k = 0; k < NB; ++k) s += red[k];
            out[0] = s * (1.0f / NB);
            g_count = 0;                // self-reset for next graph replay
        }
    }
}

extern "C" void kernel_launch(void* const* d_in, const int* in_sizes, int n_in,
                              void* d_out, int out_size) {
    const float* pred = (const float*)d_in[0];
    const float* mask = (const float*)d_in[1];
    if (n_in >= 2 && in_sizes[0] == NB * H * W && in_sizes[1] == NB * 2 * H * W) {
        mask = (const float*)d_in[0];
        pred = (const float*)d_in[1];
    }
    float* out = (float*)d_out;

    vert_kernel<<<NB * (H / RPB), 256>>>(mask);
    main_kernel<<<NBLK_B, 512>>>(pred, mask, out);
}

// round 7
// speedup vs baseline: 1.8186x; 1.1481x over previous
#include <cuda_runtime.h>
#include <cuda_fp16.h>
#include <math.h>

#define NB 16
#define H 512
#define W 512
#define KR 15
#define KKINV (1.0f/961.0f)
#define MUF 5.0f
#define RPB 16                        // rows per block in vert kernel
#define ROWS_PER_BLK 8                // rows per block in main kernel
#define NBLK_B (NB * H / ROWS_PER_BLK)   // 1024

__device__ __half2 g_vsum[NB * H * (W / 2)];   // vertical box sums, fp16 (8 MB)
__device__ float4 g_part4[NBLK_B];             // per-block partials
__device__ unsigned int g_count;               // zero-init; self-resetting

// ================= Kernel A: vertical sliding box sum (fp16 out) =================
__global__ void vert_kernel(const float* __restrict__ mask) {
    const int segs = H / RPB;        // 32
    const int b  = blockIdx.x / segs;
    const int r0 = (blockIdx.x % segs) * RPB;
    const int t  = threadIdx.x;      // 0..255, owns cols 2t, 2t+1

    const float2* mb2 = (const float2*)(mask + (size_t)b * H * W);
    __half2* vb = g_vsum + (size_t)b * H * (W / 2);

    // 4-way tree init of window [r0-15, r0+15]
    float ax[4] = {0.f, 0.f, 0.f, 0.f};
    float ay[4] = {0.f, 0.f, 0.f, 0.f};
    int lo = r0 - KR; if (lo < 0) lo = 0;
    int hi = r0 + KR; if (hi > H - 1) hi = H - 1;
    int k = 0;
    #pragma unroll 4
    for (int j = lo; j <= hi; ++j, ++k) {
        float2 v = __ldcg(&mb2[j * (W / 2) + t]);
        ax[k & 3] += v.x; ay[k & 3] += v.y;
    }
    const float ix = (ax[0] + ax[1]) + (ax[2] + ax[3]);
    const float iy = (ay[0] + ay[1]) + (ay[2] + ay[3]);

    // independent add / sub chains
    float addx = 0.f, addy = 0.f, subx = 0.f, suby = 0.f;
    #pragma unroll
    for (int rr = 0; rr < RPB; ++rr) {
        const int r = r0 + rr;
        __stcg(&vb[r * (W / 2) + t],
               __floats2half2_rn((ix + addx) - subx, (iy + addy) - suby));
        int ar = r + KR + 1;
        int sr = r - KR;
        if (ar < H) {
            float2 v = __ldcg(&mb2[ar * (W / 2) + t]);
            addx += v.x; addy += v.y;
        }
        if (sr >= 0) {
            float2 v = __ldcg(&mb2[sr * (W / 2) + t]);
            subx += v.x; suby += v.y;
        }
    }
}

// ========== Kernel B: warp-per-row horizontal box + elementwise + reduce ==========
// 256 threads = 8 warps; warp w handles row blockRow*8 + w; lane owns 16 cols
__global__ void __launch_bounds__(256)
main_kernel(const float* __restrict__ pred,
            const float* __restrict__ mask,
            float* __restrict__ out) {
    __shared__ float red[32];        // 8 warps x 4 accumulators
    __shared__ float flag;

    const int t    = threadIdx.x;
    const int wid  = t >> 5;
    const int lane = t & 31;

    const int rowg = blockIdx.x * ROWS_PER_BLK + wid;   // global row 0..8191
    const int b = rowg >> 9;
    const int r = rowg & (H - 1);
    const int c0 = lane * 16;

    // ---- global loads (issued back-to-back for MLP) ----
    const uint4* vb = (const uint4*)(g_vsum + ((size_t)b * H + r) * (W / 2));
    uint4 va = __ldcg(&vb[lane * 2 + 0]);     // 8 halves: cols c0..c0+7
    uint4 vbq = __ldcg(&vb[lane * 2 + 1]);    // cols c0+8..c0+15

    const size_t rowOff = ((size_t)b * H + r) * W;
    const float4* mrow = (const float4*)(mask + rowOff);
    const size_t predOff = (((size_t)b * 2 + 1) * H + r) * W;
    const float4* prow = (const float4*)(pred + predOff);

    float4 m4[4], p4[4];
    #pragma unroll
    for (int q = 0; q < 4; ++q) m4[q] = __ldcg(&mrow[lane * 4 + q]);
    #pragma unroll
    for (int q = 0; q < 4; ++q) p4[q] = __ldcg(&prow[lane * 4 + q]);

    // ---- unpack vsum to floats ----
    float v[16];
    {
        const __half2* ha = (const __half2*)&va;
        const __half2* hb = (const __half2*)&vbq;
        #pragma unroll
        for (int q = 0; q < 4; ++q) {
            float2 f = __half22float2(ha[q]);
            v[q * 2 + 0] = f.x; v[q * 2 + 1] = f.y;
        }
        #pragma unroll
        for (int q = 0; q < 4; ++q) {
            float2 f = __half22float2(hb[q]);
            v[8 + q * 2 + 0] = f.x; v[8 + q * 2 + 1] = f.y;
        }
    }

    // ---- local inclusive prefix over 16 cols ----
    float lp[16];
    lp[0] = v[0];
    #pragma unroll
    for (int i = 1; i < 16; ++i) lp[i] = lp[i - 1] + v[i];
    const float tot = lp[15];

    // ---- warp inclusive scan of lane totals ----
    float x = tot;
    #pragma unroll
    for (int d = 1; d < 32; d <<= 1) {
        float n = __shfl_up_sync(0xffffffffu, x, d);
        if (lane >= d) x += n;
    }
    const float e = x - tot;                          // exclusive prefix of this lane
    const float e_prev = __shfl_up_sync(0xffffffffu, e, 1);   // excl of prev lane

    float mv[16], pv[16];
    #pragma unroll
    for (int q = 0; q < 4; ++q) {
        mv[q*4+0] = m4[q].x; mv[q*4+1] = m4[q].y; mv[q*4+2] = m4[q].z; mv[q*4+3] = m4[q].w;
        pv[q*4+0] = p4[q].x; pv[q*4+1] = p4[q].y; pv[q*4+2] = p4[q].z; pv[q*4+3] = p4[q].w;
    }

    float a0 = 0.f, a1 = 0.f, a2 = 0.f, a3 = 0.f;
    #pragma unroll
    for (int i = 0; i < 16; ++i) {
        // hi = P[min(c+15, 511)]
        float hi;
        if (i == 0) {
            hi = x;                                   // own inclusive total = P[c0+15]
        } else {
            float lpn = __shfl_down_sync(0xffffffffu, lp[i - 1], 1);
            hi = (lane < 31) ? (x + lpn) : x;         // lane31: clamp to P[511] = x
        }
        // lo = (c-16 >= 0) ? P[c-16] : 0  -> prev lane's local index i
        float lpp = __shfl_up_sync(0xffffffffu, lp[i], 1);
        float lo = (lane == 0) ? 0.f : (e_prev + lpp);

        float box  = (hi - lo) * KKINV;
        float m    = mv[i];
        float p    = pv[i];
        float weit = 1.0f + MUF * fabsf(box - m);

        float eexp = __expf(-fabsf(p));                            // MUFU.EX2
        float bce  = fmaxf(p, 0.0f) - p * m + __logf(1.0f + eexp); // MUFU.LG2
        float rcp  = __fdividef(1.0f, 1.0f + eexp);                // MUFU.RCP
        float ps   = (p >= 0.0f) ? rcp : eexp * rcp;               // sigmoid(p)

        a0 += weit * bce;
        a1 += weit;
        a2 += ps * m * weit;
        a3 += (ps + m) * weit;
    }

    // ---- warp reduction ----
    #pragma unroll
    for (int d = 16; d > 0; d >>= 1) {
        a0 += __shfl_down_sync(0xffffffffu, a0, d);
        a1 += __shfl_down_sync(0xffffffffu, a1, d);
        a2 += __shfl_down_sync(0xffffffffu, a2, d);
        a3 += __shfl_down_sync(0xffffffffu, a3, d);
    }
    if (lane == 0) {
        red[wid * 4 + 0] = a0;
        red[wid * 4 + 1] = a1;
        red[wid * 4 + 2] = a2;
        red[wid * 4 + 3] = a3;
    }
    __syncthreads();

    // ---- cross-warp reduction in warp 0 (shuffle tree, no serial loop) ----
    if (wid == 0) {
        float y = red[lane];                 // lane = w*4 + k, w<8, k<4
        y += __shfl_xor_sync(0xffffffffu, y, 4);
        y += __shfl_xor_sync(0xffffffffu, y, 8);
        y += __shfl_xor_sync(0xffffffffu, y, 16);
        // lanes 0..3 now hold s0..s3
        float s0 = __shfl_sync(0xffffffffu, y, 0);
        float s1 = __shfl_sync(0xffffffffu, y, 1);
        float s2 = __shfl_sync(0xffffffffu, y, 2);
        float s3 = __shfl_sync(0xffffffffu, y, 3);
        if (lane == 0) {
            __stcg(&g_part4[blockIdx.x], make_float4(s0, s1, s2, s3));
            unsigned int old;
            asm volatile("atom.acq_rel.gpu.global.add.u32 %0, [%1], %2;"
                         : "=r"(old) : "l"(&g_count), "r"(1u) : "memory");
            flag = (old == NBLK_B - 1) ? 1.f : 0.f;
        }
    }
    __syncthreads();

    // ---------- last block finalizes ----------
    if (flag != 0.f) {
        if (t < 128) {
            const int bb = t >> 3;           // batch 0..15
            const int j  = t & 7;            // chunk 0..7
            float s0 = 0.f, s1 = 0.f, s2 = 0.f, s3 = 0.f;
            const float4* gp = g_part4 + bb * (NBLK_B / NB) + j * 8;
            #pragma unroll
            for (int kk = 0; kk < 8; ++kk) {
                float4 vv = __ldcg(&gp[kk]);
                s0 += vv.x; s1 += vv.y; s2 += vv.z; s3 += vv.w;
            }
            #pragma unroll
            for (int d = 4; d > 0; d >>= 1) {
                s0 += __shfl_down_sync(0xffffffffu, s0, d, 8);
                s1 += __shfl_down_sync(0xffffffffu, s1, d, 8);
                s2 += __shfl_down_sync(0xffffffffu, s2, d, 8);
                s3 += __shfl_down_sync(0xffffffffu, s3, d, 8);
            }
            if (j == 0) {
                float wbce = s0 / s1;
                float wiou = 1.0f - (s2 + 1.0f) / (s3 - s2 + 1.0f);
                red[bb] = wbce + wiou;
            }
        }
        __syncthreads();
        if (t == 0) {
            float s = 0.f;
            #pragma unroll
            for (int kk = 0; kk < NB; ++kk) s += red[kk];
            out[0] = s * (1.0f / NB);
            g_count = 0;                     // self-reset for next graph replay
        }
    }
}

extern "C" void kernel_launch(void* const* d_in, const int* in_sizes, int n_in,
                              void* d_out, int out_size) {
    const float* pred = (const float*)d_in[0];
    const float* mask = (const float*)d_in[1];
    if (n_in >= 2 && in_sizes[0] == NB * H * W && in_sizes[1] == NB * 2 * H * W) {
        mask = (const float*)d_in[0];
        pred = (const float*)d_in[1];
    }
    float* out = (float*)d_out;

    vert_kernel<<<NB * (H / RPB), 256>>>(mask);
    main_kernel<<<NBLK_B, 256>>>(pred, mask, out);
}